// round 1
// baseline (speedup 1.0000x reference)
#include <cuda_runtime.h>

// BoundaryConsistencyLoss — fused single-pass implementation.
// Shapes fixed by the dataset: B=512, L=16384, C=2, window=5.
//
// probs = softmax(pred, -1)[...,1] = sigmoid(p1 - p0)
// Window sums (w=5) of: m, t*m, p*m, p^2*m   (t in {0,1} -> st2m == stm)
// pvar/tvar per reference formula, mse = mean_b (pvar-tvar)^2,
// valid_w = (sum_b msum > 0), loss = sum(mse*valid)/max(sum(valid),1)

#define BB_B      512
#define LL        16384
#define WIN       5
#define NW        (LL - WIN + 1)          // 16380
#define WCHUNK    2048
#define NCHUNK    8                       // 8*2048 = 16384 covers all windows
#define CELEMS    (WCHUNK + WIN - 1)      // 2052 (divisible by 4 -> float4 ok)
#define BGROUPS   64
#define BATCHES_PER_GROUP (BB_B / BGROUPS) // 8
#define THREADS   256
#define KW        (WCHUNK / THREADS)      // 8 consecutive windows per thread

// Scratch (device globals — allocation-free). Every slot is written exactly
// once per launch, so no zeroing pass is needed and replays are deterministic.
__device__ float g_part_mse [BGROUPS * LL];
__device__ float g_part_msum[BGROUPS * LL];
__device__ float g_red[64 * 2];

__global__ __launch_bounds__(THREADS)
void bcl_accum_kernel(const float* __restrict__ preds,
                      const int*   __restrict__ targets,
                      const int*   __restrict__ mask)
{
    __shared__ __align__(16) float s_m  [CELEMS];
    __shared__ __align__(16) float s_tm [CELEMS];
    __shared__ __align__(16) float s_pm [CELEMS];
    __shared__ __align__(16) float s_p2m[CELEMS];

    const int tid = threadIdx.x;
    const int w0  = blockIdx.x * WCHUNK;
    const int b0  = blockIdx.y * BATCHES_PER_GROUP;

    float acc_mse[KW];
    float acc_msum[KW];
#pragma unroll
    for (int j = 0; j < KW; j++) { acc_mse[j] = 0.f; acc_msum[j] = 0.f; }

    for (int bi = 0; bi < BATCHES_PER_GROUP; bi++) {
        const int b = b0 + bi;
        const int rb = b * LL;

        // Stage transformed elements for this (chunk, batch) into SMEM.
        // Sigmoid computed exactly once per element.
        for (int k = tid; k < CELEMS; k += THREADS) {
            const int idx = w0 + k;
            float fm = 0.f, ft = 0.f, p = 0.f;
            if (idx < LL) {
                float2 pr = __ldg(&((const float2*)preds)[rb + idx]);
                p  = 1.0f / (1.0f + __expf(pr.x - pr.y));   // softmax[...,1]
                fm = (float)__ldg(&mask[rb + idx]);
                ft = (float)__ldg(&targets[rb + idx]);
            }
            const float pm = p * fm;
            s_m  [k] = fm;
            s_tm [k] = ft * fm;
            s_pm [k] = pm;
            s_p2m[k] = p * pm;
        }
        __syncthreads();

        // Each thread: 8 consecutive windows from 12 staged positions/array.
        const int base = tid * KW;   // byte offset base*4 is 32B-aligned
        float rm[12], rtm[12], rpm[12], rp2m[12];
#pragma unroll
        for (int q = 0; q < 3; q++) {
            float4 v;
            v = *(const float4*)&s_m  [base + q*4];
            rm  [q*4+0]=v.x; rm  [q*4+1]=v.y; rm  [q*4+2]=v.z; rm  [q*4+3]=v.w;
            v = *(const float4*)&s_tm [base + q*4];
            rtm [q*4+0]=v.x; rtm [q*4+1]=v.y; rtm [q*4+2]=v.z; rtm [q*4+3]=v.w;
            v = *(const float4*)&s_pm [base + q*4];
            rpm [q*4+0]=v.x; rpm [q*4+1]=v.y; rpm [q*4+2]=v.z; rpm [q*4+3]=v.w;
            v = *(const float4*)&s_p2m[base + q*4];
            rp2m[q*4+0]=v.x; rp2m[q*4+1]=v.y; rp2m[q*4+2]=v.z; rp2m[q*4+3]=v.w;
        }

        float sm   = rm  [0]+rm  [1]+rm  [2]+rm  [3]+rm  [4];
        float stm  = rtm [0]+rtm [1]+rtm [2]+rtm [3]+rtm [4];
        float spm  = rpm [0]+rpm [1]+rpm [2]+rpm [3]+rpm [4];
        float sp2m = rp2m[0]+rp2m[1]+rp2m[2]+rp2m[3]+rp2m[4];

#pragma unroll
        for (int j = 0; j < KW; j++) {
            const float denom = fmaxf(sm, 1.0f);
            const float rden  = __fdividef(1.0f, denom);
            const float pmean = spm * rden;
            const float pvar  = (sp2m - 2.0f*pmean*spm + pmean*pmean*sm) * rden;
            const float tmean = stm * rden;
            // st2m == stm since t,t^2 identical for t in {0,1}
            const float tvar  = (stm - 2.0f*tmean*stm + tmean*tmean*sm) * rden;
            const float d = pvar - tvar;
            acc_mse[j]  += d * d;
            acc_msum[j] += sm;
            if (j < KW - 1) {
                sm   += rm  [j+5] - rm  [j];
                stm  += rtm [j+5] - rtm [j];
                spm  += rpm [j+5] - rpm [j];
                sp2m += rp2m[j+5] - rp2m[j];
            }
        }
        __syncthreads();   // before next batch overwrites SMEM
    }

    // Write partials: one writer per slot, coalesced & vectorizable.
    const int wbase = blockIdx.y * LL + w0 + tid * KW;
#pragma unroll
    for (int j = 0; j < KW; j++) {
        g_part_mse [wbase + j] = acc_mse[j];
        g_part_msum[wbase + j] = acc_msum[j];
    }
}

__global__ __launch_bounds__(256)
void bcl_reduce_kernel()
{
    const int w = blockIdx.x * 256 + threadIdx.x;   // grid 64 -> 16384 threads
    float lmse = 0.f, lcnt = 0.f;
    if (w < NW) {
        float mse_total = 0.f, msum_total = 0.f;
#pragma unroll 8
        for (int bg = 0; bg < BGROUPS; bg++) {
            mse_total  += g_part_mse [bg * LL + w];
            msum_total += g_part_msum[bg * LL + w];
        }
        if (msum_total > 0.f) {
            lmse = mse_total * (1.0f / (float)BB_B);   // mean over batch
            lcnt = 1.0f;
        }
    }
    // block reduce (2 values)
#pragma unroll
    for (int o = 16; o > 0; o >>= 1) {
        lmse += __shfl_down_sync(0xffffffffu, lmse, o);
        lcnt += __shfl_down_sync(0xffffffffu, lcnt, o);
    }
    __shared__ float smse[8], scnt[8];
    const int wid = threadIdx.x >> 5, lid = threadIdx.x & 31;
    if (lid == 0) { smse[wid] = lmse; scnt[wid] = lcnt; }
    __syncthreads();
    if (threadIdx.x == 0) {
        float a = 0.f, c = 0.f;
#pragma unroll
        for (int i = 0; i < 8; i++) { a += smse[i]; c += scnt[i]; }
        g_red[blockIdx.x * 2 + 0] = a;
        g_red[blockIdx.x * 2 + 1] = c;
    }
}

__global__ void bcl_final_kernel(float* __restrict__ out)
{
    float a = 0.f, c = 0.f;
#pragma unroll
    for (int i = 0; i < 64; i++) {
        a += g_red[i * 2 + 0];
        c += g_red[i * 2 + 1];
    }
    out[0] = a / fmaxf(c, 1.0f);   // CONSISTENCY_WEIGHT == 1.0
}

extern "C" void kernel_launch(void* const* d_in, const int* in_sizes, int n_in,
                              void* d_out, int out_size)
{
    const float* preds   = (const float*)d_in[0];
    const int*   targets = (const int*)  d_in[1];
    const int*   mask    = (const int*)  d_in[2];

    dim3 gridB(NCHUNK, BGROUPS);            // 8 x 64 = 512 blocks
    bcl_accum_kernel<<<gridB, THREADS>>>(preds, targets, mask);
    bcl_reduce_kernel<<<64, 256>>>();
    bcl_final_kernel<<<1, 1>>>((float*)d_out);
}

// round 6
// speedup vs baseline: 1.9749x; 1.9749x over previous
#include <cuda_runtime.h>

// BoundaryConsistencyLoss — direct-from-global register-sliding version with
// explicit 1-deep prefetch across the batch-row loop.
// B=512, L=16384, C=2, window=5.
//
// p = softmax(pred,-1)[...,1] = sigmoid(p1-p0)
// Window sums (w=5) of m, t*m (int) and p*m, p^2*m (float); t in {0,1} => st2m==stm.
// pvar = sp2m/denom - pmean^2 ; tvar = tmean*(1-tmean)  (exact: msum>=1 => msum*rden==1;
// msum==0 => all sums zero, both forms give 0).

#define BB_B      512
#define LL        16384
#define WIN       5
#define NW        (LL - WIN + 1)            // 16380
#define THREADS   128
#define KW        8
#define WCHUNK    (THREADS * KW)            // 1024
#define NCHUNK    (LL / WCHUNK)             // 16
#define BGROUPS   64
#define BPG       (BB_B / BGROUPS)          // 8
#define NE        (KW + WIN - 1)            // 12 elements per thread per row

// Scratch (device globals — allocation-free). Every slot written exactly once
// per launch -> no zeroing, deterministic across graph replays.
__device__ float g_part_mse [BGROUPS * LL];
__device__ float g_part_msum[BGROUPS * LL];
__device__ float g_red[16 * 2];

__device__ __forceinline__ float fsigmoid(float x) {
    return __fdividef(1.0f, 1.0f + __expf(-x));
}

struct RowRegs {
    float4 pr[6];
    int4   tt[3], mm[3];
};

__device__ __forceinline__ void load_row(RowRegs& r,
                                         const float* __restrict__ preds,
                                         const int* __restrict__ targets,
                                         const int* __restrict__ mask,
                                         size_t rb, int base)
{
    const float4* p4 = (const float4*)preds + ((rb + (size_t)base) >> 1);
    const int4*   t4 = (const int4*)(targets + rb + base);
    const int4*   m4 = (const int4*)(mask    + rb + base);
#pragma unroll
    for (int q = 0; q < 6; q++) r.pr[q] = __ldg(&p4[q]);
#pragma unroll
    for (int q = 0; q < 3; q++) { r.tt[q] = __ldg(&t4[q]); r.mm[q] = __ldg(&m4[q]); }
}

__global__ __launch_bounds__(THREADS)
void bcl_accum_kernel(const float* __restrict__ preds,
                      const int*   __restrict__ targets,
                      const int*   __restrict__ mask)
{
    const int tid  = threadIdx.x;
    const int w0   = blockIdx.x * WCHUNK;
    const int base = w0 + tid * KW;
    const int b0   = blockIdx.y * BPG;
    const bool interior = (base + NE) <= LL;   // false only for the last thread of last chunk

    float acc_mse[KW], acc_msum[KW];
#pragma unroll
    for (int j = 0; j < KW; j++) { acc_mse[j] = 0.f; acc_msum[j] = 0.f; }

    if (interior) {
        RowRegs cur, nxt;
        load_row(cur, preds, targets, mask, (size_t)b0 * LL, base);

#pragma unroll
        for (int bi = 0; bi < BPG; bi++) {
            if (bi + 1 < BPG)
                load_row(nxt, preds, targets, mask, (size_t)(b0 + bi + 1) * LL, base);

            float pv[NE];
            int   mv[NE], tv[NE];
#pragma unroll
            for (int q = 0; q < 6; q++) {
                pv[q*2+0] = fsigmoid(cur.pr[q].y - cur.pr[q].x);
                pv[q*2+1] = fsigmoid(cur.pr[q].w - cur.pr[q].z);
            }
#pragma unroll
            for (int q = 0; q < 3; q++) {
                tv[q*4+0] = cur.tt[q].x; tv[q*4+1] = cur.tt[q].y;
                tv[q*4+2] = cur.tt[q].z; tv[q*4+3] = cur.tt[q].w;
                mv[q*4+0] = cur.mm[q].x; mv[q*4+1] = cur.mm[q].y;
                mv[q*4+2] = cur.mm[q].z; mv[q*4+3] = cur.mm[q].w;
            }

            int   tm[NE];
            float pm[NE], p2m[NE];
#pragma unroll
            for (int e = 0; e < NE; e++) {
                const int mi = mv[e];
                tm[e]  = tv[e] & mi;
                const float fm = (float)mi;
                pm[e]  = pv[e] * fm;
                p2m[e] = pv[e] * pm[e];
            }

            int   smi  = mv[0]+mv[1]+mv[2]+mv[3]+mv[4];
            int   stmi = tm[0]+tm[1]+tm[2]+tm[3]+tm[4];
            float spm  = pm[0]+pm[1]+pm[2]+pm[3]+pm[4];
            float sp2m = p2m[0]+p2m[1]+p2m[2]+p2m[3]+p2m[4];

#pragma unroll
            for (int j = 0; j < KW; j++) {
                const float sm    = (float)smi;
                const float rden  = __fdividef(1.0f, fmaxf(sm, 1.0f));
                const float pmean = spm * rden;
                const float pvar  = sp2m * rden - pmean * pmean;
                const float tmean = (float)stmi * rden;
                const float tvar  = tmean - tmean * tmean;
                const float d = pvar - tvar;
                acc_mse[j]  += d * d;
                acc_msum[j] += sm;
                if (j < KW - 1) {
                    smi  += mv[j+WIN] - mv[j];
                    stmi += tm[j+WIN] - tm[j];
                    spm  += pm[j+WIN] - pm[j];
                    sp2m += p2m[j+WIN] - p2m[j];
                }
            }
            cur = nxt;
        }
    } else {
        // tail thread: guarded scalar path (rare, correctness only)
        for (int bi = 0; bi < BPG; bi++) {
            const size_t rb = (size_t)(b0 + bi) * LL;
            float pv[NE]; int mv[NE], tv[NE];
#pragma unroll
            for (int e = 0; e < NE; e++) {
                const int idx = base + e;
                if (idx < LL) {
                    float a = __ldg(&preds[(rb + idx) * 2 + 0]);
                    float b = __ldg(&preds[(rb + idx) * 2 + 1]);
                    pv[e] = fsigmoid(b - a);
                    tv[e] = __ldg(&targets[rb + idx]);
                    mv[e] = __ldg(&mask[rb + idx]);
                } else { pv[e] = 0.f; tv[e] = 0; mv[e] = 0; }
            }
            int tm[NE]; float pm[NE], p2m[NE];
#pragma unroll
            for (int e = 0; e < NE; e++) {
                const int mi = mv[e];
                tm[e] = tv[e] & mi;
                const float fm = (float)mi;
                pm[e] = pv[e] * fm;
                p2m[e] = pv[e] * pm[e];
            }
            int   smi  = mv[0]+mv[1]+mv[2]+mv[3]+mv[4];
            int   stmi = tm[0]+tm[1]+tm[2]+tm[3]+tm[4];
            float spm  = pm[0]+pm[1]+pm[2]+pm[3]+pm[4];
            float sp2m = p2m[0]+p2m[1]+p2m[2]+p2m[3]+p2m[4];
#pragma unroll
            for (int j = 0; j < KW; j++) {
                const float sm    = (float)smi;
                const float rden  = __fdividef(1.0f, fmaxf(sm, 1.0f));
                const float pmean = spm * rden;
                const float pvar  = sp2m * rden - pmean * pmean;
                const float tmean = (float)stmi * rden;
                const float tvar  = tmean - tmean * tmean;
                const float d = pvar - tvar;
                acc_mse[j]  += d * d;
                acc_msum[j] += sm;
                if (j < KW - 1) {
                    smi  += mv[j+WIN] - mv[j];
                    stmi += tm[j+WIN] - tm[j];
                    spm  += pm[j+WIN] - pm[j];
                    sp2m += p2m[j+WIN] - p2m[j];
                }
            }
        }
    }

    float4* om = (float4*)&g_part_mse [blockIdx.y * LL + base];
    float4* os = (float4*)&g_part_msum[blockIdx.y * LL + base];
    om[0] = make_float4(acc_mse[0], acc_mse[1], acc_mse[2], acc_mse[3]);
    om[1] = make_float4(acc_mse[4], acc_mse[5], acc_mse[6], acc_mse[7]);
    os[0] = make_float4(acc_msum[0], acc_msum[1], acc_msum[2], acc_msum[3]);
    os[1] = make_float4(acc_msum[4], acc_msum[5], acc_msum[6], acc_msum[7]);
}

__global__ __launch_bounds__(256)
void bcl_reduce_kernel()
{
    const int w4 = (blockIdx.x * 256 + threadIdx.x) * 4;
    float4 mse_t  = make_float4(0.f, 0.f, 0.f, 0.f);
    float4 msum_t = make_float4(0.f, 0.f, 0.f, 0.f);
#pragma unroll 4
    for (int bg = 0; bg < BGROUPS; bg++) {
        float4 a = *(const float4*)&g_part_mse [bg * LL + w4];
        float4 b = *(const float4*)&g_part_msum[bg * LL + w4];
        mse_t.x += a.x;  mse_t.y += a.y;  mse_t.z += a.z;  mse_t.w += a.w;
        msum_t.x += b.x; msum_t.y += b.y; msum_t.z += b.z; msum_t.w += b.w;
    }
    float lmse = 0.f, lcnt = 0.f;
    const float inv_b = 1.0f / (float)BB_B;
    {
        const float* me = &mse_t.x;
        const float* ms = &msum_t.x;
#pragma unroll
        for (int k = 0; k < 4; k++) {
            if (w4 + k < NW && ms[k] > 0.f) { lmse += me[k] * inv_b; lcnt += 1.f; }
        }
    }
#pragma unroll
    for (int o = 16; o > 0; o >>= 1) {
        lmse += __shfl_down_sync(0xffffffffu, lmse, o);
        lcnt += __shfl_down_sync(0xffffffffu, lcnt, o);
    }
    __shared__ float smse[8], scnt[8];
    const int wid = threadIdx.x >> 5, lid = threadIdx.x & 31;
    if (lid == 0) { smse[wid] = lmse; scnt[wid] = lcnt; }
    __syncthreads();
    if (threadIdx.x == 0) {
        float a = 0.f, c = 0.f;
#pragma unroll
        for (int i = 0; i < 8; i++) { a += smse[i]; c += scnt[i]; }
        g_red[blockIdx.x * 2 + 0] = a;
        g_red[blockIdx.x * 2 + 1] = c;
    }
}

__global__ void bcl_final_kernel(float* __restrict__ out)
{
    float a = 0.f, c = 0.f;
#pragma unroll
    for (int i = 0; i < 16; i++) {
        a += g_red[i * 2 + 0];
        c += g_red[i * 2 + 1];
    }
    out[0] = a / fmaxf(c, 1.0f);   // CONSISTENCY_WEIGHT == 1.0
}

extern "C" void kernel_launch(void* const* d_in, const int* in_sizes, int n_in,
                              void* d_out, int out_size)
{
    const float* preds   = (const float*)d_in[0];
    const int*   targets = (const int*)  d_in[1];
    const int*   mask    = (const int*)  d_in[2];

    dim3 gridA(NCHUNK, BGROUPS);             // 16 x 64 = 1024 blocks
    bcl_accum_kernel<<<gridA, THREADS>>>(preds, targets, mask);
    bcl_reduce_kernel<<<16, 256>>>();
    bcl_final_kernel<<<1, 1>>>((float*)d_out);
}

// round 8
// speedup vs baseline: 2.2724x; 1.1506x over previous
#include <cuda_runtime.h>

// BoundaryConsistencyLoss — direct-from-global register-sliding version,
// 1-deep row prefetch, bitmask validity (OR instead of msum-sum), and a
// fully parallel reduction.
// B=512, L=16384, C=2, window=5.
//
// p = softmax(pred,-1)[...,1] = sigmoid(p1-p0)
// Window sums (w=5) of m, t*m (int) and p*m, p^2*m (float); t in {0,1} => st2m==stm.
// pvar = sp2m/denom - pmean^2 ; tvar = tmean*(1-tmean)  (exact: msum>=1 => msum*rden==1;
// msum==0 => all sums zero => both 0).
// valid_w = (sum_b msum > 0)  ===  OR over batches of (window has any mask bit).

#define BB_B      512
#define LL        16384
#define WIN       5
#define NW        (LL - WIN + 1)            // 16380
#define THREADS   128
#define KW        8
#define WCHUNK    (THREADS * KW)            // 1024
#define NCHUNK    (LL / WCHUNK)             // 16
#define BGROUPS   64
#define BPG       (BB_B / BGROUPS)          // 8
#define NE        (KW + WIN - 1)            // 12 elements per thread per row
#define VBYTES    (LL / 8)                  // 2048 validity bytes per group

// Scratch (device globals — allocation-free). Every slot written exactly once
// per launch -> no zeroing, deterministic across graph replays.
__device__ float         g_part_mse[BGROUPS * LL];
__device__ unsigned char g_valid   [BGROUPS * VBYTES];
__device__ float         g_red[64 * 2];

__device__ __forceinline__ float fsigmoid(float x) {
    return __fdividef(1.0f, 1.0f + __expf(-x));
}

struct RowRegs {
    float4 pr[6];
    int4   tt[3], mm[3];
};

__device__ __forceinline__ void load_row(RowRegs& r,
                                         const float* __restrict__ preds,
                                         const int* __restrict__ targets,
                                         const int* __restrict__ mask,
                                         size_t rb, int base)
{
    const float4* p4 = (const float4*)preds + ((rb + (size_t)base) >> 1);
    const int4*   t4 = (const int4*)(targets + rb + base);
    const int4*   m4 = (const int4*)(mask    + rb + base);
#pragma unroll
    for (int q = 0; q < 6; q++) r.pr[q] = __ldg(&p4[q]);
#pragma unroll
    for (int q = 0; q < 3; q++) { r.tt[q] = __ldg(&t4[q]); r.mm[q] = __ldg(&m4[q]); }
}

__global__ __launch_bounds__(THREADS)
void bcl_accum_kernel(const float* __restrict__ preds,
                      const int*   __restrict__ targets,
                      const int*   __restrict__ mask)
{
    const int tid  = threadIdx.x;
    const int w0   = blockIdx.x * WCHUNK;
    const int base = w0 + tid * KW;
    const int b0   = blockIdx.y * BPG;
    const bool interior = (base + NE) <= LL;   // false only for last thread of last chunk

    float acc_mse[KW];
#pragma unroll
    for (int j = 0; j < KW; j++) acc_mse[j] = 0.f;
    unsigned vmask = 0;                        // bit j: window base+j had any mask

    if (interior) {
        RowRegs cur, nxt;
        load_row(cur, preds, targets, mask, (size_t)b0 * LL, base);

#pragma unroll
        for (int bi = 0; bi < BPG; bi++) {
            if (bi + 1 < BPG)
                load_row(nxt, preds, targets, mask, (size_t)(b0 + bi + 1) * LL, base);

            float pv[NE];
            int   mv[NE], tv[NE];
#pragma unroll
            for (int q = 0; q < 6; q++) {
                pv[q*2+0] = fsigmoid(cur.pr[q].y - cur.pr[q].x);
                pv[q*2+1] = fsigmoid(cur.pr[q].w - cur.pr[q].z);
            }
#pragma unroll
            for (int q = 0; q < 3; q++) {
                tv[q*4+0] = cur.tt[q].x; tv[q*4+1] = cur.tt[q].y;
                tv[q*4+2] = cur.tt[q].z; tv[q*4+3] = cur.tt[q].w;
                mv[q*4+0] = cur.mm[q].x; mv[q*4+1] = cur.mm[q].y;
                mv[q*4+2] = cur.mm[q].z; mv[q*4+3] = cur.mm[q].w;
            }

            int   tm[NE];
            float pm[NE], p2m[NE];
#pragma unroll
            for (int e = 0; e < NE; e++) {
                const int mi = mv[e];
                tm[e]  = tv[e] & mi;
                const float fm = (float)mi;
                pm[e]  = pv[e] * fm;
                p2m[e] = pv[e] * pm[e];
            }

            int   smi  = mv[0]+mv[1]+mv[2]+mv[3]+mv[4];
            int   stmi = tm[0]+tm[1]+tm[2]+tm[3]+tm[4];
            float spm  = pm[0]+pm[1]+pm[2]+pm[3]+pm[4];
            float sp2m = p2m[0]+p2m[1]+p2m[2]+p2m[3]+p2m[4];

#pragma unroll
            for (int j = 0; j < KW; j++) {
                const float sm    = (float)smi;
                const float rden  = __fdividef(1.0f, fmaxf(sm, 1.0f));
                const float pmean = spm * rden;
                const float pvar  = sp2m * rden - pmean * pmean;
                const float tmean = (float)stmi * rden;
                const float tvar  = tmean - tmean * tmean;
                const float d = pvar - tvar;
                acc_mse[j] += d * d;
                vmask |= (unsigned)(smi != 0) << j;
                if (j < KW - 1) {
                    smi  += mv[j+WIN] - mv[j];
                    stmi += tm[j+WIN] - tm[j];
                    spm  += pm[j+WIN] - pm[j];
                    sp2m += p2m[j+WIN] - p2m[j];
                }
            }
            cur = nxt;
        }
    } else {
        // tail thread: guarded scalar path (rare, correctness only)
        for (int bi = 0; bi < BPG; bi++) {
            const size_t rb = (size_t)(b0 + bi) * LL;
            float pv[NE]; int mv[NE], tv[NE];
#pragma unroll
            for (int e = 0; e < NE; e++) {
                const int idx = base + e;
                if (idx < LL) {
                    float a = __ldg(&preds[(rb + idx) * 2 + 0]);
                    float b = __ldg(&preds[(rb + idx) * 2 + 1]);
                    pv[e] = fsigmoid(b - a);
                    tv[e] = __ldg(&targets[rb + idx]);
                    mv[e] = __ldg(&mask[rb + idx]);
                } else { pv[e] = 0.f; tv[e] = 0; mv[e] = 0; }
            }
            int tm[NE]; float pm[NE], p2m[NE];
#pragma unroll
            for (int e = 0; e < NE; e++) {
                const int mi = mv[e];
                tm[e] = tv[e] & mi;
                const float fm = (float)mi;
                pm[e] = pv[e] * fm;
                p2m[e] = pv[e] * pm[e];
            }
            int   smi  = mv[0]+mv[1]+mv[2]+mv[3]+mv[4];
            int   stmi = tm[0]+tm[1]+tm[2]+tm[3]+tm[4];
            float spm  = pm[0]+pm[1]+pm[2]+pm[3]+pm[4];
            float sp2m = p2m[0]+p2m[1]+p2m[2]+p2m[3]+p2m[4];
#pragma unroll
            for (int j = 0; j < KW; j++) {
                const float sm    = (float)smi;
                const float rden  = __fdividef(1.0f, fmaxf(sm, 1.0f));
                const float pmean = spm * rden;
                const float pvar  = sp2m * rden - pmean * pmean;
                const float tmean = (float)stmi * rden;
                const float tvar  = tmean - tmean * tmean;
                const float d = pvar - tvar;
                acc_mse[j] += d * d;
                vmask |= (unsigned)(smi != 0) << j;
                if (j < KW - 1) {
                    smi  += mv[j+WIN] - mv[j];
                    stmi += tm[j+WIN] - tm[j];
                    spm  += pm[j+WIN] - pm[j];
                    sp2m += p2m[j+WIN] - p2m[j];
                }
            }
        }
    }

    // Partials: float4 x2 for mse, 1 validity byte per thread (coalesced).
    float4* om = (float4*)&g_part_mse[blockIdx.y * LL + base];
    om[0] = make_float4(acc_mse[0], acc_mse[1], acc_mse[2], acc_mse[3]);
    om[1] = make_float4(acc_mse[4], acc_mse[5], acc_mse[6], acc_mse[7]);
    g_valid[blockIdx.y * VBYTES + (base >> 3)] = (unsigned char)vmask;
}

__global__ __launch_bounds__(256)
void bcl_reduce_kernel()
{
    // 64 blocks x 256 threads: one window per thread, 64 group-partials each.
    const int w = blockIdx.x * 256 + threadIdx.x;

    // Validity bytes for this block's 256 windows = 32 bytes; OR across groups.
    __shared__ unsigned char svalid[32];
    if (threadIdx.x < 32) {
        const int bidx = blockIdx.x * 32 + threadIdx.x;
        unsigned v = 0;
#pragma unroll 8
        for (int bg = 0; bg < BGROUPS; bg++)
            v |= (unsigned)g_valid[bg * VBYTES + bidx];
        svalid[threadIdx.x] = (unsigned char)v;
    }
    __syncthreads();

    float mse_total = 0.f;
#pragma unroll 8
    for (int bg = 0; bg < BGROUPS; bg++)
        mse_total += g_part_mse[bg * LL + w];

    float lmse = 0.f, lcnt = 0.f;
    if (w < NW && ((svalid[threadIdx.x >> 3] >> (w & 7)) & 1)) {
        lmse = mse_total * (1.0f / (float)BB_B);
        lcnt = 1.f;
    }

#pragma unroll
    for (int o = 16; o > 0; o >>= 1) {
        lmse += __shfl_down_sync(0xffffffffu, lmse, o);
        lcnt += __shfl_down_sync(0xffffffffu, lcnt, o);
    }
    __shared__ float smse[8], scnt[8];
    const int wid = threadIdx.x >> 5, lid = threadIdx.x & 31;
    if (lid == 0) { smse[wid] = lmse; scnt[wid] = lcnt; }
    __syncthreads();
    if (threadIdx.x == 0) {
        float a = 0.f, c = 0.f;
#pragma unroll
        for (int i = 0; i < 8; i++) { a += smse[i]; c += scnt[i]; }
        g_red[blockIdx.x * 2 + 0] = a;
        g_red[blockIdx.x * 2 + 1] = c;
    }
}

__global__ void bcl_final_kernel(float* __restrict__ out)
{
    float a = 0.f, c = 0.f;
#pragma unroll
    for (int i = 0; i < 64; i++) {
        a += g_red[i * 2 + 0];
        c += g_red[i * 2 + 1];
    }
    out[0] = a / fmaxf(c, 1.0f);   // CONSISTENCY_WEIGHT == 1.0
}

extern "C" void kernel_launch(void* const* d_in, const int* in_sizes, int n_in,
                              void* d_out, int out_size)
{
    const float* preds   = (const float*)d_in[0];
    const int*   targets = (const int*)  d_in[1];
    const int*   mask    = (const int*)  d_in[2];

    dim3 gridA(NCHUNK, BGROUPS);             // 16 x 64 = 1024 blocks
    bcl_accum_kernel<<<gridA, THREADS>>>(preds, targets, mask);
    bcl_reduce_kernel<<<64, 256>>>();
    bcl_final_kernel<<<1, 1>>>((float*)d_out);
}

// round 10
// speedup vs baseline: 2.6357x; 1.1599x over previous
#include <cuda_runtime.h>

// BoundaryConsistencyLoss — direct-from-global register-sliding, KW=4 for 2x
// thread-level parallelism, 1-deep row prefetch, bitmask validity, parallel
// reduction.  B=512, L=16384, C=2, window=5.
//
// p = softmax(pred,-1)[...,1] = sigmoid(p1-p0)
// Window sums (w=5) of m, t*m (int) and p*m, p^2*m (float); t in {0,1} => st2m==stm.
// pvar = sp2m/denom - pmean^2 ; tvar = tmean*(1-tmean)  (exact; msum==0 => both 0).
// valid_w = (sum_b msum > 0) === OR over batches of (window has any mask).

#define BB_B      512
#define LL        16384
#define WIN       5
#define NW        (LL - WIN + 1)            // 16380
#define THREADS   128
#define KW        4
#define WCHUNK    (THREADS * KW)            // 512
#define NCHUNK    (LL / WCHUNK)             // 32
#define BGROUPS   64
#define BPG       (BB_B / BGROUPS)          // 8
#define NE        (KW + WIN - 1)            // 8 elements per thread per row
#define VBYTES    (LL / KW)                 // 4096 validity bytes per group

// Scratch (device globals — allocation-free). Every slot written exactly once
// per launch -> no zeroing, deterministic across graph replays.
__device__ float         g_part_mse[BGROUPS * LL];
__device__ unsigned char g_valid   [BGROUPS * VBYTES];
__device__ float         g_red[64 * 2];

__device__ __forceinline__ float fsigmoid(float x) {
    return __fdividef(1.0f, 1.0f + __expf(-x));
}

struct RowRegs {
    float4 pr[4];          // 8 pred pairs
    int4   tt[2], mm[2];   // 8 targets, 8 masks
};

__device__ __forceinline__ void load_row(RowRegs& r,
                                         const float* __restrict__ preds,
                                         const int* __restrict__ targets,
                                         const int* __restrict__ mask,
                                         size_t rb, int base)
{
    const float4* p4 = (const float4*)preds + ((rb + (size_t)base) >> 1);
    const int4*   t4 = (const int4*)(targets + rb + base);
    const int4*   m4 = (const int4*)(mask    + rb + base);
#pragma unroll
    for (int q = 0; q < 4; q++) r.pr[q] = __ldg(&p4[q]);
#pragma unroll
    for (int q = 0; q < 2; q++) { r.tt[q] = __ldg(&t4[q]); r.mm[q] = __ldg(&m4[q]); }
}

__global__ __launch_bounds__(THREADS)
void bcl_accum_kernel(const float* __restrict__ preds,
                      const int*   __restrict__ targets,
                      const int*   __restrict__ mask)
{
    const int tid  = threadIdx.x;
    const int w0   = blockIdx.x * WCHUNK;
    const int base = w0 + tid * KW;
    const int b0   = blockIdx.y * BPG;
    const bool interior = (base + NE) <= LL;   // false only for last thread of last chunk

    float acc_mse[KW];
#pragma unroll
    for (int j = 0; j < KW; j++) acc_mse[j] = 0.f;
    unsigned vmask = 0;                        // bit j: window base+j had any mask

    if (interior) {
        RowRegs cur, nxt;
        load_row(cur, preds, targets, mask, (size_t)b0 * LL, base);

#pragma unroll
        for (int bi = 0; bi < BPG; bi++) {
            if (bi + 1 < BPG)
                load_row(nxt, preds, targets, mask, (size_t)(b0 + bi + 1) * LL, base);

            float pv[NE];
            int   mv[NE], tv[NE];
#pragma unroll
            for (int q = 0; q < 4; q++) {
                pv[q*2+0] = fsigmoid(cur.pr[q].y - cur.pr[q].x);
                pv[q*2+1] = fsigmoid(cur.pr[q].w - cur.pr[q].z);
            }
#pragma unroll
            for (int q = 0; q < 2; q++) {
                tv[q*4+0] = cur.tt[q].x; tv[q*4+1] = cur.tt[q].y;
                tv[q*4+2] = cur.tt[q].z; tv[q*4+3] = cur.tt[q].w;
                mv[q*4+0] = cur.mm[q].x; mv[q*4+1] = cur.mm[q].y;
                mv[q*4+2] = cur.mm[q].z; mv[q*4+3] = cur.mm[q].w;
            }

            int   tm[NE];
            float pm[NE], p2m[NE];
#pragma unroll
            for (int e = 0; e < NE; e++) {
                const int mi = mv[e];
                tm[e]  = tv[e] & mi;
                const float fm = (float)mi;
                pm[e]  = pv[e] * fm;
                p2m[e] = pv[e] * pm[e];
            }

            int   smi  = mv[0]+mv[1]+mv[2]+mv[3]+mv[4];
            int   stmi = tm[0]+tm[1]+tm[2]+tm[3]+tm[4];
            float spm  = pm[0]+pm[1]+pm[2]+pm[3]+pm[4];
            float sp2m = p2m[0]+p2m[1]+p2m[2]+p2m[3]+p2m[4];

#pragma unroll
            for (int j = 0; j < KW; j++) {
                const float sm    = (float)smi;
                const float rden  = __fdividef(1.0f, fmaxf(sm, 1.0f));
                const float pmean = spm * rden;
                const float pvar  = sp2m * rden - pmean * pmean;
                const float tmean = (float)stmi * rden;
                const float tvar  = tmean - tmean * tmean;
                const float d = pvar - tvar;
                acc_mse[j] += d * d;
                vmask |= (unsigned)(smi != 0) << j;
                if (j < KW - 1) {
                    smi  += mv[j+WIN] - mv[j];
                    stmi += tm[j+WIN] - tm[j];
                    spm  += pm[j+WIN] - pm[j];
                    sp2m += p2m[j+WIN] - p2m[j];
                }
            }
            cur = nxt;
        }
    } else {
        // tail thread: guarded scalar path (rare, correctness only)
        for (int bi = 0; bi < BPG; bi++) {
            const size_t rb = (size_t)(b0 + bi) * LL;
            float pv[NE]; int mv[NE], tv[NE];
#pragma unroll
            for (int e = 0; e < NE; e++) {
                const int idx = base + e;
                if (idx < LL) {
                    float a = __ldg(&preds[(rb + idx) * 2 + 0]);
                    float b = __ldg(&preds[(rb + idx) * 2 + 1]);
                    pv[e] = fsigmoid(b - a);
                    tv[e] = __ldg(&targets[rb + idx]);
                    mv[e] = __ldg(&mask[rb + idx]);
                } else { pv[e] = 0.f; tv[e] = 0; mv[e] = 0; }
            }
            int tm[NE]; float pm[NE], p2m[NE];
#pragma unroll
            for (int e = 0; e < NE; e++) {
                const int mi = mv[e];
                tm[e] = tv[e] & mi;
                const float fm = (float)mi;
                pm[e] = pv[e] * fm;
                p2m[e] = pv[e] * pm[e];
            }
            int   smi  = mv[0]+mv[1]+mv[2]+mv[3]+mv[4];
            int   stmi = tm[0]+tm[1]+tm[2]+tm[3]+tm[4];
            float spm  = pm[0]+pm[1]+pm[2]+pm[3]+pm[4];
            float sp2m = p2m[0]+p2m[1]+p2m[2]+p2m[3]+p2m[4];
#pragma unroll
            for (int j = 0; j < KW; j++) {
                const float sm    = (float)smi;
                const float rden  = __fdividef(1.0f, fmaxf(sm, 1.0f));
                const float pmean = spm * rden;
                const float pvar  = sp2m * rden - pmean * pmean;
                const float tmean = (float)stmi * rden;
                const float tvar  = tmean - tmean * tmean;
                const float d = pvar - tvar;
                acc_mse[j] += d * d;
                vmask |= (unsigned)(smi != 0) << j;
                if (j < KW - 1) {
                    smi  += mv[j+WIN] - mv[j];
                    stmi += tm[j+WIN] - tm[j];
                    spm  += pm[j+WIN] - pm[j];
                    sp2m += p2m[j+WIN] - p2m[j];
                }
            }
        }
    }

    // Partials: one float4 of mse, one validity byte per thread (coalesced).
    *(float4*)&g_part_mse[blockIdx.y * LL + base] =
        make_float4(acc_mse[0], acc_mse[1], acc_mse[2], acc_mse[3]);
    g_valid[blockIdx.y * VBYTES + (base >> 2)] = (unsigned char)vmask;
}

__global__ __launch_bounds__(256)
void bcl_reduce_kernel()
{
    // 64 blocks x 256 threads: one window per thread, 64 group-partials each.
    const int w = blockIdx.x * 256 + threadIdx.x;

    // Validity bytes for this block's 256 windows = 64 bytes; OR across groups.
    __shared__ unsigned char svalid[64];
    if (threadIdx.x < 64) {
        const int bidx = blockIdx.x * 64 + threadIdx.x;
        unsigned v = 0;
#pragma unroll 8
        for (int bg = 0; bg < BGROUPS; bg++)
            v |= (unsigned)g_valid[bg * VBYTES + bidx];
        svalid[threadIdx.x] = (unsigned char)v;
    }
    __syncthreads();

    float mse_total = 0.f;
#pragma unroll 8
    for (int bg = 0; bg < BGROUPS; bg++)
        mse_total += g_part_mse[bg * LL + w];

    float lmse = 0.f, lcnt = 0.f;
    if (w < NW && ((svalid[threadIdx.x >> 2] >> (w & 3)) & 1)) {
        lmse = mse_total * (1.0f / (float)BB_B);
        lcnt = 1.f;
    }

#pragma unroll
    for (int o = 16; o > 0; o >>= 1) {
        lmse += __shfl_down_sync(0xffffffffu, lmse, o);
        lcnt += __shfl_down_sync(0xffffffffu, lcnt, o);
    }
    __shared__ float smse[8], scnt[8];
    const int wid = threadIdx.x >> 5, lid = threadIdx.x & 31;
    if (lid == 0) { smse[wid] = lmse; scnt[wid] = lcnt; }
    __syncthreads();
    if (threadIdx.x == 0) {
        float a = 0.f, c = 0.f;
#pragma unroll
        for (int i = 0; i < 8; i++) { a += smse[i]; c += scnt[i]; }
        g_red[blockIdx.x * 2 + 0] = a;
        g_red[blockIdx.x * 2 + 1] = c;
    }
}

__global__ void bcl_final_kernel(float* __restrict__ out)
{
    float a = 0.f, c = 0.f;
#pragma unroll
    for (int i = 0; i < 64; i++) {
        a += g_red[i * 2 + 0];
        c += g_red[i * 2 + 1];
    }
    out[0] = a / fmaxf(c, 1.0f);   // CONSISTENCY_WEIGHT == 1.0
}

extern "C" void kernel_launch(void* const* d_in, const int* in_sizes, int n_in,
                              void* d_out, int out_size)
{
    const float* preds   = (const float*)d_in[0];
    const int*   targets = (const int*)  d_in[1];
    const int*   mask    = (const int*)  d_in[2];

    dim3 gridA(NCHUNK, BGROUPS);             // 32 x 64 = 2048 blocks
    bcl_accum_kernel<<<gridA, THREADS>>>(preds, targets, mask);
    bcl_reduce_kernel<<<64, 256>>>();
    bcl_final_kernel<<<1, 1>>>((float*)d_out);
}

// round 11
// speedup vs baseline: 2.7097x; 1.0281x over previous
#include <cuda_runtime.h>

// BoundaryConsistencyLoss — direct-from-global register-sliding accum (KW=4,
// 1-deep row prefetch, bitmask validity) + two-stage parallel reduction.
// B=512, L=16384, C=2, window=5.
//
// p = softmax(pred,-1)[...,1] = sigmoid(p1-p0)
// Window sums (w=5) of m, t*m (int) and p*m, p^2*m (float); t in {0,1} => st2m==stm.
// pvar = sp2m/denom - pmean^2 ; tvar = tmean*(1-tmean)  (exact; msum==0 => both 0).
// valid_w = (sum_b msum > 0) === OR over batches of (window has any mask).

#define BB_B      512
#define LL        16384
#define WIN       5
#define NW        (LL - WIN + 1)            // 16380
#define THREADS   128
#define KW        4
#define WCHUNK    (THREADS * KW)            // 512
#define NCHUNK    (LL / WCHUNK)             // 32
#define BGROUPS   64
#define BPG       (BB_B / BGROUPS)          // 8
#define NE        (KW + WIN - 1)            // 8 elements per thread per row
#define VBYTES    (LL / KW)                 // 4096 validity bytes per group
#define R1G       8                         // reduce stage-1 output groups

// Scratch (device globals — allocation-free). Every slot written exactly once
// per launch -> no zeroing, deterministic across graph replays.
__device__ float         g_part_mse[BGROUPS * LL];
__device__ unsigned char g_valid   [BGROUPS * VBYTES];
__device__ float         g_part2   [R1G * LL];
__device__ float         g_red[64 * 2];

__device__ __forceinline__ float fsigmoid(float x) {
    return __fdividef(1.0f, 1.0f + __expf(-x));
}

struct RowRegs {
    float4 pr[4];          // 8 pred pairs
    int4   tt[2], mm[2];   // 8 targets, 8 masks
};

__device__ __forceinline__ void load_row(RowRegs& r,
                                         const float* __restrict__ preds,
                                         const int* __restrict__ targets,
                                         const int* __restrict__ mask,
                                         size_t rb, int base)
{
    const float4* p4 = (const float4*)preds + ((rb + (size_t)base) >> 1);
    const int4*   t4 = (const int4*)(targets + rb + base);
    const int4*   m4 = (const int4*)(mask    + rb + base);
#pragma unroll
    for (int q = 0; q < 4; q++) r.pr[q] = __ldg(&p4[q]);
#pragma unroll
    for (int q = 0; q < 2; q++) { r.tt[q] = __ldg(&t4[q]); r.mm[q] = __ldg(&m4[q]); }
}

__global__ __launch_bounds__(THREADS)
void bcl_accum_kernel(const float* __restrict__ preds,
                      const int*   __restrict__ targets,
                      const int*   __restrict__ mask)
{
    const int tid  = threadIdx.x;
    const int w0   = blockIdx.x * WCHUNK;
    const int base = w0 + tid * KW;
    const int b0   = blockIdx.y * BPG;
    const bool interior = (base + NE) <= LL;   // false only for last thread of last chunk

    float acc_mse[KW];
#pragma unroll
    for (int j = 0; j < KW; j++) acc_mse[j] = 0.f;
    unsigned vmask = 0;                        // bit j: window base+j had any mask

    if (interior) {
        RowRegs cur, nxt;
        load_row(cur, preds, targets, mask, (size_t)b0 * LL, base);

#pragma unroll
        for (int bi = 0; bi < BPG; bi++) {
            if (bi + 1 < BPG)
                load_row(nxt, preds, targets, mask, (size_t)(b0 + bi + 1) * LL, base);

            float pv[NE];
            int   mv[NE], tv[NE];
#pragma unroll
            for (int q = 0; q < 4; q++) {
                pv[q*2+0] = fsigmoid(cur.pr[q].y - cur.pr[q].x);
                pv[q*2+1] = fsigmoid(cur.pr[q].w - cur.pr[q].z);
            }
#pragma unroll
            for (int q = 0; q < 2; q++) {
                tv[q*4+0] = cur.tt[q].x; tv[q*4+1] = cur.tt[q].y;
                tv[q*4+2] = cur.tt[q].z; tv[q*4+3] = cur.tt[q].w;
                mv[q*4+0] = cur.mm[q].x; mv[q*4+1] = cur.mm[q].y;
                mv[q*4+2] = cur.mm[q].z; mv[q*4+3] = cur.mm[q].w;
            }

            int   tm[NE];
            float pm[NE], p2m[NE];
#pragma unroll
            for (int e = 0; e < NE; e++) {
                const int mi = mv[e];
                tm[e]  = tv[e] & mi;
                const float fm = (float)mi;
                pm[e]  = pv[e] * fm;
                p2m[e] = pv[e] * pm[e];
            }

            int   smi  = mv[0]+mv[1]+mv[2]+mv[3]+mv[4];
            int   stmi = tm[0]+tm[1]+tm[2]+tm[3]+tm[4];
            float spm  = pm[0]+pm[1]+pm[2]+pm[3]+pm[4];
            float sp2m = p2m[0]+p2m[1]+p2m[2]+p2m[3]+p2m[4];

#pragma unroll
            for (int j = 0; j < KW; j++) {
                const float sm    = (float)smi;
                const float rden  = __fdividef(1.0f, fmaxf(sm, 1.0f));
                const float pmean = spm * rden;
                const float pvar  = sp2m * rden - pmean * pmean;
                const float tmean = (float)stmi * rden;
                const float tvar  = tmean - tmean * tmean;
                const float d = pvar - tvar;
                acc_mse[j] += d * d;
                vmask |= (unsigned)(smi != 0) << j;
                if (j < KW - 1) {
                    smi  += mv[j+WIN] - mv[j];
                    stmi += tm[j+WIN] - tm[j];
                    spm  += pm[j+WIN] - pm[j];
                    sp2m += p2m[j+WIN] - p2m[j];
                }
            }
            cur = nxt;
        }
    } else {
        // tail thread: guarded scalar path (rare, correctness only)
        for (int bi = 0; bi < BPG; bi++) {
            const size_t rb = (size_t)(b0 + bi) * LL;
            float pv[NE]; int mv[NE], tv[NE];
#pragma unroll
            for (int e = 0; e < NE; e++) {
                const int idx = base + e;
                if (idx < LL) {
                    float a = __ldg(&preds[(rb + idx) * 2 + 0]);
                    float b = __ldg(&preds[(rb + idx) * 2 + 1]);
                    pv[e] = fsigmoid(b - a);
                    tv[e] = __ldg(&targets[rb + idx]);
                    mv[e] = __ldg(&mask[rb + idx]);
                } else { pv[e] = 0.f; tv[e] = 0; mv[e] = 0; }
            }
            int tm[NE]; float pm[NE], p2m[NE];
#pragma unroll
            for (int e = 0; e < NE; e++) {
                const int mi = mv[e];
                tm[e] = tv[e] & mi;
                const float fm = (float)mi;
                pm[e] = pv[e] * fm;
                p2m[e] = pv[e] * pm[e];
            }
            int   smi  = mv[0]+mv[1]+mv[2]+mv[3]+mv[4];
            int   stmi = tm[0]+tm[1]+tm[2]+tm[3]+tm[4];
            float spm  = pm[0]+pm[1]+pm[2]+pm[3]+pm[4];
            float sp2m = p2m[0]+p2m[1]+p2m[2]+p2m[3]+p2m[4];
#pragma unroll
            for (int j = 0; j < KW; j++) {
                const float sm    = (float)smi;
                const float rden  = __fdividef(1.0f, fmaxf(sm, 1.0f));
                const float pmean = spm * rden;
                const float pvar  = sp2m * rden - pmean * pmean;
                const float tmean = (float)stmi * rden;
                const float tvar  = tmean - tmean * tmean;
                const float d = pvar - tvar;
                acc_mse[j] += d * d;
                vmask |= (unsigned)(smi != 0) << j;
                if (j < KW - 1) {
                    smi  += mv[j+WIN] - mv[j];
                    stmi += tm[j+WIN] - tm[j];
                    spm  += pm[j+WIN] - pm[j];
                    sp2m += p2m[j+WIN] - p2m[j];
                }
            }
        }
    }

    // Partials: one float4 of mse, one validity byte per thread (coalesced).
    *(float4*)&g_part_mse[blockIdx.y * LL + base] =
        make_float4(acc_mse[0], acc_mse[1], acc_mse[2], acc_mse[3]);
    g_valid[blockIdx.y * VBYTES + (base >> 2)] = (unsigned char)vmask;
}

// Reduce stage 1: sum 8 groups per output slot. grid (64, 8) x 256.
__global__ __launch_bounds__(256)
void bcl_reduce1_kernel()
{
    const int w  = blockIdx.x * 256 + threadIdx.x;
    const int g0 = blockIdx.y * (BGROUPS / R1G);   // 8 groups per y-slice
    float s = 0.f;
#pragma unroll
    for (int g = 0; g < BGROUPS / R1G; g++)
        s += g_part_mse[(g0 + g) * LL + w];
    g_part2[blockIdx.y * LL + w] = s;
}

// Reduce stage 2: sum 8 stage-1 partials + validity OR + block reduce. grid 64 x 256.
__global__ __launch_bounds__(256)
void bcl_reduce2_kernel()
{
    const int w = blockIdx.x * 256 + threadIdx.x;

    // Validity bytes for this block's 256 windows = 64 bytes; OR across groups.
    __shared__ unsigned char svalid[64];
    if (threadIdx.x < 64) {
        const int bidx = blockIdx.x * 64 + threadIdx.x;
        unsigned v = 0;
#pragma unroll 8
        for (int bg = 0; bg < BGROUPS; bg++)
            v |= (unsigned)g_valid[bg * VBYTES + bidx];
        svalid[threadIdx.x] = (unsigned char)v;
    }
    __syncthreads();

    float mse_total = 0.f;
#pragma unroll
    for (int r = 0; r < R1G; r++)
        mse_total += g_part2[r * LL + w];

    float lmse = 0.f, lcnt = 0.f;
    if (w < NW && ((svalid[threadIdx.x >> 2] >> (w & 3)) & 1)) {
        lmse = mse_total * (1.0f / (float)BB_B);
        lcnt = 1.f;
    }

#pragma unroll
    for (int o = 16; o > 0; o >>= 1) {
        lmse += __shfl_down_sync(0xffffffffu, lmse, o);
        lcnt += __shfl_down_sync(0xffffffffu, lcnt, o);
    }
    __shared__ float smse[8], scnt[8];
    const int wid = threadIdx.x >> 5, lid = threadIdx.x & 31;
    if (lid == 0) { smse[wid] = lmse; scnt[wid] = lcnt; }
    __syncthreads();
    if (threadIdx.x == 0) {
        float a = 0.f, c = 0.f;
#pragma unroll
        for (int i = 0; i < 8; i++) { a += smse[i]; c += scnt[i]; }
        g_red[blockIdx.x * 2 + 0] = a;
        g_red[blockIdx.x * 2 + 1] = c;
    }
}

__global__ __launch_bounds__(64)
void bcl_final_kernel(float* __restrict__ out)
{
    // 64 threads: thread i loads pair i, warp+smem reduce.
    const int i = threadIdx.x;
    float a = g_red[i * 2 + 0];
    float c = g_red[i * 2 + 1];
#pragma unroll
    for (int o = 16; o > 0; o >>= 1) {
        a += __shfl_down_sync(0xffffffffu, a, o);
        c += __shfl_down_sync(0xffffffffu, c, o);
    }
    __shared__ float sa[2], sc[2];
    if ((i & 31) == 0) { sa[i >> 5] = a; sc[i >> 5] = c; }
    __syncthreads();
    if (i == 0) {
        const float ta = sa[0] + sa[1];
        const float tc = sc[0] + sc[1];
        out[0] = ta / fmaxf(tc, 1.0f);   // CONSISTENCY_WEIGHT == 1.0
    }
}

extern "C" void kernel_launch(void* const* d_in, const int* in_sizes, int n_in,
                              void* d_out, int out_size)
{
    const float* preds   = (const float*)d_in[0];
    const int*   targets = (const int*)  d_in[1];
    const int*   mask    = (const int*)  d_in[2];

    dim3 gridA(NCHUNK, BGROUPS);             // 32 x 64 = 2048 blocks
    bcl_accum_kernel<<<gridA, THREADS>>>(preds, targets, mask);
    dim3 gridR1(64, R1G);                    // 512 blocks x 256 threads
    bcl_reduce1_kernel<<<gridR1, 256>>>();
    bcl_reduce2_kernel<<<64, 256>>>();
    bcl_final_kernel<<<1, 64>>>((float*)d_out);
}